// round 1
// baseline (speedup 1.0000x reference)
#include <cuda_runtime.h>

#define L_MAX 4096
#define NH    12
#define DK    64
#define DM    768
#define SPAD  68   // 64 + 4 pad, keeps float4 alignment

// ---------------- scratch (allocation-free rule: __device__ globals) ----------------
__device__ float g_Qh[NH * L_MAX * DK];
__device__ float g_Kh[NH * L_MAX * DK];
__device__ float g_Vh[NH * L_MAX * DK];
__device__ float g_Ctx[L_MAX * DM];

// ---------------- GEMM core: out = A(MxK) @ W^T (W is NxK row-major) + bias ----------------
// BM=BN=128, BK=16, 256 threads, 8x8 micro-tile per thread.
template <bool HEAD_SPLIT>
__device__ __forceinline__ void gemm_core(const float* __restrict__ A,
                                          const float* __restrict__ W,
                                          const float* __restrict__ bias,
                                          float* __restrict__ out,
                                          int L)
{
    const int K = DM;  // 768
    __shared__ float As[16][128];
    __shared__ float Bs[16][128];

    const int tid = threadIdx.x;
    const int tx  = tid & 15;
    const int ty  = tid >> 4;
    const int m0  = blockIdx.x * 128;
    const int n0  = blockIdx.y * 128;

    float acc[8][8];
#pragma unroll
    for (int i = 0; i < 8; i++)
#pragma unroll
        for (int j = 0; j < 8; j++) acc[i][j] = 0.0f;

    for (int k0 = 0; k0 < K; k0 += 16) {
#pragma unroll
        for (int i = 0; i < 2; i++) {
            int slot = tid + i * 256;      // 0..511
            int m    = slot >> 2;          // 0..127
            int kq   = (slot & 3) << 2;    // 0,4,8,12
            float4 va = *(const float4*)(A + (size_t)(m0 + m) * K + k0 + kq);
            As[kq + 0][m] = va.x; As[kq + 1][m] = va.y;
            As[kq + 2][m] = va.z; As[kq + 3][m] = va.w;
            float4 vb = *(const float4*)(W + (size_t)(n0 + m) * K + k0 + kq);
            Bs[kq + 0][m] = vb.x; Bs[kq + 1][m] = vb.y;
            Bs[kq + 2][m] = vb.z; Bs[kq + 3][m] = vb.w;
        }
        __syncthreads();

#pragma unroll
        for (int kk = 0; kk < 16; kk++) {
            float a[8], b[8];
            *(float4*)&a[0] = *(const float4*)&As[kk][ty * 8];
            *(float4*)&a[4] = *(const float4*)&As[kk][ty * 8 + 4];
            *(float4*)&b[0] = *(const float4*)&Bs[kk][tx * 8];
            *(float4*)&b[4] = *(const float4*)&Bs[kk][tx * 8 + 4];
#pragma unroll
            for (int i = 0; i < 8; i++)
#pragma unroll
                for (int j = 0; j < 8; j++)
                    acc[i][j] = fmaf(a[i], b[j], acc[i][j]);
        }
        __syncthreads();
    }

#pragma unroll
    for (int i = 0; i < 8; i++) {
        int m = m0 + ty * 8 + i;
#pragma unroll
        for (int j = 0; j < 8; j++) {
            int n = n0 + tx * 8 + j;
            float v = acc[i][j] + bias[n];
            if (HEAD_SPLIT) {
                // layout (head, l, dk)
                out[((size_t)(n >> 6) * L + m) * DK + (n & 63)] = v;
            } else {
                out[(size_t)m * DM + n] = v;
            }
        }
    }
}

__global__ void __launch_bounds__(256) qkv_proj_kernel(
    const float* __restrict__ q, const float* __restrict__ k, const float* __restrict__ v,
    const float* __restrict__ Wq, const float* __restrict__ bq,
    const float* __restrict__ Wk, const float* __restrict__ bk,
    const float* __restrict__ Wv, const float* __restrict__ bv,
    int L)
{
    if (blockIdx.z == 0)      gemm_core<true>(q, Wq, bq, g_Qh, L);
    else if (blockIdx.z == 1) gemm_core<true>(k, Wk, bk, g_Kh, L);
    else                      gemm_core<true>(v, Wv, bv, g_Vh, L);
}

__global__ void __launch_bounds__(256) out_proj_kernel(
    const float* __restrict__ Wo, const float* __restrict__ bo,
    float* __restrict__ out, int L)
{
    gemm_core<false>(g_Ctx, Wo, bo, out, L);
}

// ---------------- Flash attention: 64 queries x 64 keys per tile, d=64 ----------------
// 256 threads = 16x16 (ty,tx).
// S-phase: thread owns query rows {ty+16i}, key cols {tx+16j}  (conflict-free strided LDS.128)
// PV-phase: thread owns query rows {ty+16i}, dim cols {tx*4+j} (vectorized V loads)
__global__ void __launch_bounds__(256) flash_kernel(int L)
{
    extern __shared__ float sm[];
    float* Qs = sm;                  // 64*SPAD
    float* Ks = Qs + 64 * SPAD;
    float* Vs = Ks + 64 * SPAD;
    float* Ps = Vs + 64 * SPAD;

    const int h   = blockIdx.y;
    const int q0  = blockIdx.x * 64;
    const int tid = threadIdx.x;
    const int tx  = tid & 15;
    const int ty  = tid >> 4;

    const float* Qb = g_Qh + ((size_t)h * L + q0) * DK;
    const float* Kb = g_Kh + (size_t)h * L * DK;
    const float* Vb = g_Vh + (size_t)h * L * DK;

    // load Q tile once
#pragma unroll
    for (int i = 0; i < 4; i++) {
        int slot = tid + i * 256;     // 0..1023
        int r    = slot >> 4;
        int c    = (slot & 15) << 2;
        *(float4*)&Qs[r * SPAD + c] = *(const float4*)(Qb + (size_t)r * DK + c);
    }

    float m[4], l[4], acc[4][4];
#pragma unroll
    for (int i = 0; i < 4; i++) {
        m[i] = -1e30f;
        l[i] = 0.0f;
#pragma unroll
        for (int j = 0; j < 4; j++) acc[i][j] = 0.0f;
    }

    const int nt = L >> 6;
    for (int t = 0; t < nt; t++) {
        __syncthreads();   // prior iteration's Vs/Ps reads are done
        const float* Kt = Kb + (size_t)t * 64 * DK;
        const float* Vt = Vb + (size_t)t * 64 * DK;
#pragma unroll
        for (int i = 0; i < 4; i++) {
            int slot = tid + i * 256;
            int r    = slot >> 4;
            int c    = (slot & 15) << 2;
            *(float4*)&Ks[r * SPAD + c] = *(const float4*)(Kt + (size_t)r * DK + c);
            *(float4*)&Vs[r * SPAD + c] = *(const float4*)(Vt + (size_t)r * DK + c);
        }
        __syncthreads();

        // S = Q K^T
        float s[4][4];
#pragma unroll
        for (int i = 0; i < 4; i++)
#pragma unroll
            for (int j = 0; j < 4; j++) s[i][j] = 0.0f;

#pragma unroll
        for (int kk = 0; kk < 64; kk += 4) {
            float4 qv[4], kv[4];
#pragma unroll
            for (int i = 0; i < 4; i++) qv[i] = *(const float4*)&Qs[(ty + i * 16) * SPAD + kk];
#pragma unroll
            for (int j = 0; j < 4; j++) kv[j] = *(const float4*)&Ks[(tx + j * 16) * SPAD + kk];
#pragma unroll
            for (int i = 0; i < 4; i++)
#pragma unroll
                for (int j = 0; j < 4; j++)
                    s[i][j] += qv[i].x * kv[j].x + qv[i].y * kv[j].y +
                               qv[i].z * kv[j].z + qv[i].w * kv[j].w;
        }

        // online softmax update + stage P to shared
#pragma unroll
        for (int i = 0; i < 4; i++) {
#pragma unroll
            for (int j = 0; j < 4; j++) s[i][j] *= 0.125f;  // 1/sqrt(64)
            float rm = fmaxf(fmaxf(s[i][0], s[i][1]), fmaxf(s[i][2], s[i][3]));
#pragma unroll
            for (int o = 1; o < 16; o <<= 1)
                rm = fmaxf(rm, __shfl_xor_sync(0xffffffffu, rm, o));
            float mn   = fmaxf(m[i], rm);
            float corr = __expf(m[i] - mn);
            float rs   = 0.0f;
#pragma unroll
            for (int j = 0; j < 4; j++) {
                s[i][j] = __expf(s[i][j] - mn);
                rs += s[i][j];
            }
#pragma unroll
            for (int o = 1; o < 16; o <<= 1)
                rs += __shfl_xor_sync(0xffffffffu, rs, o);
            l[i] = l[i] * corr + rs;
            m[i] = mn;
#pragma unroll
            for (int j = 0; j < 4; j++) {
                acc[i][j] *= corr;
                Ps[(ty + i * 16) * SPAD + tx + j * 16] = s[i][j];
            }
        }
        __syncthreads();

        // acc += P V
#pragma unroll
        for (int kk = 0; kk < 64; kk += 4) {
            float4 p4[4], v4[4];
#pragma unroll
            for (int i = 0; i < 4; i++) p4[i] = *(const float4*)&Ps[(ty + i * 16) * SPAD + kk];
#pragma unroll
            for (int r = 0; r < 4; r++) v4[r] = *(const float4*)&Vs[(kk + r) * SPAD + tx * 4];
#pragma unroll
            for (int i = 0; i < 4; i++) {
                acc[i][0] += p4[i].x * v4[0].x + p4[i].y * v4[1].x + p4[i].z * v4[2].x + p4[i].w * v4[3].x;
                acc[i][1] += p4[i].x * v4[0].y + p4[i].y * v4[1].y + p4[i].z * v4[2].y + p4[i].w * v4[3].y;
                acc[i][2] += p4[i].x * v4[0].z + p4[i].y * v4[1].z + p4[i].z * v4[2].z + p4[i].w * v4[3].z;
                acc[i][3] += p4[i].x * v4[0].w + p4[i].y * v4[1].w + p4[i].z * v4[2].w + p4[i].w * v4[3].w;
            }
        }
    }

    // epilogue: normalize, write context in (L, DM) layout
#pragma unroll
    for (int i = 0; i < 4; i++) {
        float inv = 1.0f / l[i];
        int row   = q0 + ty + i * 16;
        float4 o4 = make_float4(acc[i][0] * inv, acc[i][1] * inv,
                                acc[i][2] * inv, acc[i][3] * inv);
        *(float4*)&g_Ctx[(size_t)row * DM + h * DK + tx * 4] = o4;
    }
}

// ---------------- launch ----------------
extern "C" void kernel_launch(void* const* d_in, const int* in_sizes, int n_in,
                              void* d_out, int out_size)
{
    const float* q  = (const float*)d_in[0];
    const float* k  = (const float*)d_in[1];
    const float* v  = (const float*)d_in[2];
    const float* Wq = (const float*)d_in[3];
    const float* bq = (const float*)d_in[4];
    const float* Wk = (const float*)d_in[5];
    const float* bk = (const float*)d_in[6];
    const float* Wv = (const float*)d_in[7];
    const float* bv = (const float*)d_in[8];
    const float* Wo = (const float*)d_in[9];
    const float* bo = (const float*)d_in[10];
    float* out = (float*)d_out;

    const int L = in_sizes[0] / DM;   // 4096

    const int flash_smem = 4 * 64 * SPAD * (int)sizeof(float);  // 69632 B
    cudaFuncSetAttribute(flash_kernel,
                         cudaFuncAttributeMaxDynamicSharedMemorySize, flash_smem);

    dim3 gqkv(L / 128, DM / 128, 3);
    qkv_proj_kernel<<<gqkv, 256>>>(q, k, v, Wq, bq, Wk, bk, Wv, bv, L);

    dim3 gfl(L / 64, NH, 1);
    flash_kernel<<<gfl, 256, flash_smem>>>(L);

    dim3 gop(L / 128, DM / 128, 1);
    out_proj_kernel<<<gop, 256>>>(Wo, bo, out, L);
}

// round 2
// speedup vs baseline: 1.0001x; 1.0001x over previous
#include <cuda_runtime.h>

#define L_MAX 4096
#define NH    12
#define DK    64
#define DM    768
#define SPAD  68   // 64 + 4 pad, keeps float4 alignment

// ---------------- scratch (allocation-free rule: __device__ globals) ----------------
__device__ float g_Qh[NH * L_MAX * DK];
__device__ float g_Kh[NH * L_MAX * DK];
__device__ float g_Vh[NH * L_MAX * DK];
__device__ float g_Ctx[L_MAX * DM];

// ---------------- GEMM core: out = A(MxK) @ W^T (W is NxK row-major) + bias ----------------
// BM=BN=128, BK=16, 256 threads, 8x8 micro-tile per thread.
template <bool HEAD_SPLIT>
__device__ __forceinline__ void gemm_core(const float* __restrict__ A,
                                          const float* __restrict__ W,
                                          const float* __restrict__ bias,
                                          float* __restrict__ out,
                                          int L)
{
    const int K = DM;  // 768
    __shared__ float As[16][128];
    __shared__ float Bs[16][128];

    const int tid = threadIdx.x;
    const int tx  = tid & 15;
    const int ty  = tid >> 4;
    const int m0  = blockIdx.x * 128;
    const int n0  = blockIdx.y * 128;

    float acc[8][8];
#pragma unroll
    for (int i = 0; i < 8; i++)
#pragma unroll
        for (int j = 0; j < 8; j++) acc[i][j] = 0.0f;

    for (int k0 = 0; k0 < K; k0 += 16) {
#pragma unroll
        for (int i = 0; i < 2; i++) {
            int slot = tid + i * 256;      // 0..511
            int m    = slot >> 2;          // 0..127
            int kq   = (slot & 3) << 2;    // 0,4,8,12
            float4 va = *(const float4*)(A + (size_t)(m0 + m) * K + k0 + kq);
            As[kq + 0][m] = va.x; As[kq + 1][m] = va.y;
            As[kq + 2][m] = va.z; As[kq + 3][m] = va.w;
            float4 vb = *(const float4*)(W + (size_t)(n0 + m) * K + k0 + kq);
            Bs[kq + 0][m] = vb.x; Bs[kq + 1][m] = vb.y;
            Bs[kq + 2][m] = vb.z; Bs[kq + 3][m] = vb.w;
        }
        __syncthreads();

#pragma unroll
        for (int kk = 0; kk < 16; kk++) {
            float a[8], b[8];
            *(float4*)&a[0] = *(const float4*)&As[kk][ty * 8];
            *(float4*)&a[4] = *(const float4*)&As[kk][ty * 8 + 4];
            *(float4*)&b[0] = *(const float4*)&Bs[kk][tx * 8];
            *(float4*)&b[4] = *(const float4*)&Bs[kk][tx * 8 + 4];
#pragma unroll
            for (int i = 0; i < 8; i++)
#pragma unroll
                for (int j = 0; j < 8; j++)
                    acc[i][j] = fmaf(a[i], b[j], acc[i][j]);
        }
        __syncthreads();
    }

#pragma unroll
    for (int i = 0; i < 8; i++) {
        int m = m0 + ty * 8 + i;
#pragma unroll
        for (int j = 0; j < 8; j++) {
            int n = n0 + tx * 8 + j;
            float v = acc[i][j] + bias[n];
            if (HEAD_SPLIT) {
                // layout (head, l, dk)
                out[((size_t)(n >> 6) * L + m) * DK + (n & 63)] = v;
            } else {
                out[(size_t)m * DM + n] = v;
            }
        }
    }
}

__global__ void __launch_bounds__(256) qkv_proj_kernel(
    const float* __restrict__ q, const float* __restrict__ k, const float* __restrict__ v,
    const float* __restrict__ Wq, const float* __restrict__ bq,
    const float* __restrict__ Wk, const float* __restrict__ bk,
    const float* __restrict__ Wv, const float* __restrict__ bv,
    int L)
{
    if (blockIdx.z == 0)      gemm_core<true>(q, Wq, bq, g_Qh, L);
    else if (blockIdx.z == 1) gemm_core<true>(k, Wk, bk, g_Kh, L);
    else                      gemm_core<true>(v, Wv, bv, g_Vh, L);
}

__global__ void __launch_bounds__(256) out_proj_kernel(
    const float* __restrict__ Wo, const float* __restrict__ bo,
    float* __restrict__ out, int L)
{
    gemm_core<false>(g_Ctx, Wo, bo, out, L);
}

// ---------------- Flash attention: 64 queries x 64 keys per tile, d=64 ----------------
// 256 threads = 16x16 (ty,tx).
// S-phase: thread owns query rows {ty+16i}, key cols {tx+16j}  (conflict-free strided LDS.128)
// PV-phase: thread owns query rows {ty+16i}, dim cols {tx*4+j} (vectorized V loads)
__global__ void __launch_bounds__(256) flash_kernel(int L)
{
    extern __shared__ float sm[];
    float* Qs = sm;                  // 64*SPAD
    float* Ks = Qs + 64 * SPAD;
    float* Vs = Ks + 64 * SPAD;
    float* Ps = Vs + 64 * SPAD;

    const int h   = blockIdx.y;
    const int q0  = blockIdx.x * 64;
    const int tid = threadIdx.x;
    const int tx  = tid & 15;
    const int ty  = tid >> 4;

    const float* Qb = g_Qh + ((size_t)h * L + q0) * DK;
    const float* Kb = g_Kh + (size_t)h * L * DK;
    const float* Vb = g_Vh + (size_t)h * L * DK;

    // load Q tile once
#pragma unroll
    for (int i = 0; i < 4; i++) {
        int slot = tid + i * 256;     // 0..1023
        int r    = slot >> 4;
        int c    = (slot & 15) << 2;
        *(float4*)&Qs[r * SPAD + c] = *(const float4*)(Qb + (size_t)r * DK + c);
    }

    float m[4], l[4], acc[4][4];
#pragma unroll
    for (int i = 0; i < 4; i++) {
        m[i] = -1e30f;
        l[i] = 0.0f;
#pragma unroll
        for (int j = 0; j < 4; j++) acc[i][j] = 0.0f;
    }

    const int nt = L >> 6;
    for (int t = 0; t < nt; t++) {
        __syncthreads();   // prior iteration's Vs/Ps reads are done
        const float* Kt = Kb + (size_t)t * 64 * DK;
        const float* Vt = Vb + (size_t)t * 64 * DK;
#pragma unroll
        for (int i = 0; i < 4; i++) {
            int slot = tid + i * 256;
            int r    = slot >> 4;
            int c    = (slot & 15) << 2;
            *(float4*)&Ks[r * SPAD + c] = *(const float4*)(Kt + (size_t)r * DK + c);
            *(float4*)&Vs[r * SPAD + c] = *(const float4*)(Vt + (size_t)r * DK + c);
        }
        __syncthreads();

        // S = Q K^T
        float s[4][4];
#pragma unroll
        for (int i = 0; i < 4; i++)
#pragma unroll
            for (int j = 0; j < 4; j++) s[i][j] = 0.0f;

#pragma unroll
        for (int kk = 0; kk < 64; kk += 4) {
            float4 qv[4], kv[4];
#pragma unroll
            for (int i = 0; i < 4; i++) qv[i] = *(const float4*)&Qs[(ty + i * 16) * SPAD + kk];
#pragma unroll
            for (int j = 0; j < 4; j++) kv[j] = *(const float4*)&Ks[(tx + j * 16) * SPAD + kk];
#pragma unroll
            for (int i = 0; i < 4; i++)
#pragma unroll
                for (int j = 0; j < 4; j++)
                    s[i][j] += qv[i].x * kv[j].x + qv[i].y * kv[j].y +
                               qv[i].z * kv[j].z + qv[i].w * kv[j].w;
        }

        // online softmax update + stage P to shared
#pragma unroll
        for (int i = 0; i < 4; i++) {
#pragma unroll
            for (int j = 0; j < 4; j++) s[i][j] *= 0.125f;  // 1/sqrt(64)
            float rm = fmaxf(fmaxf(s[i][0], s[i][1]), fmaxf(s[i][2], s[i][3]));
#pragma unroll
            for (int o = 1; o < 16; o <<= 1)
                rm = fmaxf(rm, __shfl_xor_sync(0xffffffffu, rm, o));
            float mn   = fmaxf(m[i], rm);
            float corr = __expf(m[i] - mn);
            float rs   = 0.0f;
#pragma unroll
            for (int j = 0; j < 4; j++) {
                s[i][j] = __expf(s[i][j] - mn);
                rs += s[i][j];
            }
#pragma unroll
            for (int o = 1; o < 16; o <<= 1)
                rs += __shfl_xor_sync(0xffffffffu, rs, o);
            l[i] = l[i] * corr + rs;
            m[i] = mn;
#pragma unroll
            for (int j = 0; j < 4; j++) {
                acc[i][j] *= corr;
                Ps[(ty + i * 16) * SPAD + tx + j * 16] = s[i][j];
            }
        }
        __syncthreads();

        // acc += P V
#pragma unroll
        for (int kk = 0; kk < 64; kk += 4) {
            float4 p4[4], v4[4];
#pragma unroll
            for (int i = 0; i < 4; i++) p4[i] = *(const float4*)&Ps[(ty + i * 16) * SPAD + kk];
#pragma unroll
            for (int r = 0; r < 4; r++) v4[r] = *(const float4*)&Vs[(kk + r) * SPAD + tx * 4];
#pragma unroll
            for (int i = 0; i < 4; i++) {
                acc[i][0] += p4[i].x * v4[0].x + p4[i].y * v4[1].x + p4[i].z * v4[2].x + p4[i].w * v4[3].x;
                acc[i][1] += p4[i].x * v4[0].y + p4[i].y * v4[1].y + p4[i].z * v4[2].y + p4[i].w * v4[3].y;
                acc[i][2] += p4[i].x * v4[0].z + p4[i].y * v4[1].z + p4[i].z * v4[2].z + p4[i].w * v4[3].z;
                acc[i][3] += p4[i].x * v4[0].w + p4[i].y * v4[1].w + p4[i].z * v4[2].w + p4[i].w * v4[3].w;
            }
        }
    }

    // epilogue: normalize, write context in (L, DM) layout
#pragma unroll
    for (int i = 0; i < 4; i++) {
        float inv = 1.0f / l[i];
        int row   = q0 + ty + i * 16;
        float4 o4 = make_float4(acc[i][0] * inv, acc[i][1] * inv,
                                acc[i][2] * inv, acc[i][3] * inv);
        *(float4*)&g_Ctx[(size_t)row * DM + h * DK + tx * 4] = o4;
    }
}

// ---------------- launch ----------------
extern "C" void kernel_launch(void* const* d_in, const int* in_sizes, int n_in,
                              void* d_out, int out_size)
{
    const float* q  = (const float*)d_in[0];
    const float* k  = (const float*)d_in[1];
    const float* v  = (const float*)d_in[2];
    const float* Wq = (const float*)d_in[3];
    const float* bq = (const float*)d_in[4];
    const float* Wk = (const float*)d_in[5];
    const float* bk = (const float*)d_in[6];
    const float* Wv = (const float*)d_in[7];
    const float* bv = (const float*)d_in[8];
    const float* Wo = (const float*)d_in[9];
    const float* bo = (const float*)d_in[10];
    float* out = (float*)d_out;

    const int L = in_sizes[0] / DM;   // 4096

    const int flash_smem = 4 * 64 * SPAD * (int)sizeof(float);  // 69632 B
    cudaFuncSetAttribute(flash_kernel,
                         cudaFuncAttributeMaxDynamicSharedMemorySize, flash_smem);

    dim3 gqkv(L / 128, DM / 128, 3);
    qkv_proj_kernel<<<gqkv, 256>>>(q, k, v, Wq, bq, Wk, bk, Wv, bv, L);

    dim3 gfl(L / 64, NH, 1);
    flash_kernel<<<gfl, 256, flash_smem>>>(L);

    dim3 gop(L / 128, DM / 128, 1);
    out_proj_kernel<<<gop, 256>>>(Wo, bo, out, L);
}